// round 17
// baseline (speedup 1.0000x reference)
#include <cuda_runtime.h>
#include <cuda_fp16.h>
#include <cstdint>

#define HH 384
#define WW 384
#define CC 32
#define FF 32
#define KK 9
#define POS_PER_BLK 64
#define THREADS 512

// A: 128 rows x 288 fp16, row padded to 640 B
// K-column order: col(k,c) = (k>>1)*64 + 2c + (k&1) for k<8 ; 256 + c for k==8
#define ROWB 640u
#define SMEM_A_OFF 0u
#define A_BYTES (128u * ROWB)                  // 81920
#define ROW1_DELTA (64u * ROWB)                // batch-1 row offset
// B: 32 rows x 288 fp16, row 640 B (same K order)
#define SMEM_B_OFF A_BYTES                     // 81920
#define B_BYTES (32u * ROWB)                   // 20480
#define SMEM_TOTAL (SMEM_B_OFF + B_BYTES)      // 102400  (2 CTAs/SM)

#define NPIXC (HH * WW * CC)
#define NTAPS (HH * WW * KK)                   // 1327104 records

// Pre-swizzled fp16 B tile + batch-interleaved fp16 x image + per-tap records
__device__ __align__(16) char d_Btile[B_BYTES];
__device__ __align__(16) __half2 d_xh[NPIXC];        // [pix][c] = (x_b0, x_b1)
__device__ __align__(16) uint4 d_recs[NTAPS];        // one 16B record per (pixel, tap)

__device__ __forceinline__ uint32_t smem_u32(const void* p) {
    uint32_t a;
    asm("{ .reg .u64 t; cvta.to.shared.u64 t, %1; cvt.u32.u64 %0, t; }" : "=r"(a) : "l"(p));
    return a;
}

#define LDMATRIX_X4(r0, r1, r2, r3, addr)                                   \
    asm volatile("ldmatrix.sync.aligned.m8n8.x4.shared.b16 {%0,%1,%2,%3}, [%4];" \
                 : "=r"(r0), "=r"(r1), "=r"(r2), "=r"(r3) : "r"(addr))

#define MMA16816(d, a0, a1, a2, a3, b0, b1)                                 \
    asm volatile("mma.sync.aligned.m16n8k16.row.col.f32.f16.f16.f32 "       \
                 "{%0,%1,%2,%3}, {%4,%5,%6,%7}, {%8,%9}, {%0,%1,%2,%3};"    \
                 : "+f"((d)[0]), "+f"((d)[1]), "+f"((d)[2]), "+f"((d)[3])   \
                 : "r"(a0), "r"(a1), "r"(a2), "r"(a3), "r"(b0), "r"(b1))

__device__ __forceinline__ uint32_t swz_addr(uint32_t kb, uint32_t rm) {
    return (kb & ~127u) + ((((kb >> 4) & 7u) ^ rm) << 4) + (kb & 15u);
}

// ---- merged prep: half2 x image + swizzled fp16 B tile + per-tap records ----
// GRID MUST COVER max(NPIXC/4, NTAPS) threads (records are the larger domain).
__global__ void prep_kernel(const float* __restrict__ x,
                            const float* __restrict__ kern,
                            const float* __restrict__ off) {
    const int i = blockIdx.x * blockDim.x + threadIdx.x;
    const int base = i * 4;
    if (base < NPIXC) {
        const float4 a = __ldg((const float4*)(x + base));
        const float4 b = __ldg((const float4*)(x + NPIXC + base));
        uint4 o;
        const __half2 h0 = __floats2half2_rn(a.x, b.x);
        const __half2 h1 = __floats2half2_rn(a.y, b.y);
        const __half2 h2 = __floats2half2_rn(a.z, b.z);
        const __half2 h3 = __floats2half2_rn(a.w, b.w);
        o.x = *(const uint32_t*)&h0;
        o.y = *(const uint32_t*)&h1;
        o.z = *(const uint32_t*)&h2;
        o.w = *(const uint32_t*)&h3;
        *(uint4*)(d_xh + base) = o;
    }
    if (i < KK * CC * FF) {
        const int f = i & 31;
        const int c = (i >> 5) & 31;
        const int k = i >> 10;
        const __half wh = __float2half_rn(__ldg(kern + (k * 32 + c) * 32 + f));
        const uint32_t kb = (k < 8)
            ? (uint32_t)((k >> 1) * 128 + c * 4 + (k & 1) * 2)
            : (uint32_t)(512 + c * 2);
        *(__half*)(d_Btile + (uint32_t)f * ROWB + swz_addr(kb, (uint32_t)f & 7u)) = wh;
    }
    if (i < NTAPS) {
        // record for tap i: pixel pos_g = i/9, tap k = i%9; off index = i*2 floats
        const int pos_g = i / KK;
        const int k = i - pos_g * KK;
        const int y = pos_g / WW;
        const int xcol = pos_g - y * WW;
        const float2 o = __ldg((const float2*)(off + (size_t)i * 2));

        // padded coords: tap base (y + k/3, x + k%3), pad=1, clamp to [0,385]
        float yf = fminf(fmaxf((float)(y + k / 3) + o.y, 0.f), 385.f);
        float xf = fminf(fmaxf((float)(xcol + k % 3) + o.x, 0.f), 385.f);
        const float y0f = floorf(yf), x0f = floorf(xf);
        const int y0 = (int)y0f, x0 = (int)x0f;
        const int y1 = min(y0 + 1, 385), x1 = min(x0 + 1, 385);
        const float wy0 = (float)y1 - yf, wy1 = yf - y0f;
        const float wx0 = (float)x1 - xf, wx1 = xf - x0f;

        const bool vy0 = (y0 >= 1) && (y0 <= 384);
        const bool vy1 = (y1 >= 1) && (y1 <= 384);
        const bool vx0 = (x0 >= 1) && (x0 <= 384);
        const bool vx1 = (x1 >= 1) && (x1 <= 384);
        const float w00 = (vy0 && vx0) ? wy0 * wx0 : 0.f;
        const float w01 = (vy0 && vx1) ? wy0 * wx1 : 0.f;
        const float w10 = (vy1 && vx0) ? wy1 * wx0 : 0.f;
        const float w11 = (vy1 && vx1) ? wy1 * wx1 : 0.f;

        const int y0c = min(max(y0, 1), 384), y1c = min(max(y1, 1), 384);
        const int x0c = min(max(x0, 1), 384), x1c = min(max(x1, 1), 384);
        const uint32_t i00b = (uint32_t)(((y0c - 1) * WW + (x0c - 1)) * CC) * 4u;
        const uint32_t dxb = (uint32_t)((x1c - x0c) * CC) * 4u;        // 0 or 128
        const uint32_t dyb = (uint32_t)((y1c - y0c) * WW * CC) * 4u;   // 0 or 49152

        const __half2 wA = __floats2half2_rn(w00, w01);
        const __half2 wB = __floats2half2_rn(w10, w11);
        uint4 rec;
        rec.x = i00b;
        rec.y = dxb | (dyb << 16);
        rec.z = *(const uint32_t*)&wA;
        rec.w = *(const uint32_t*)&wB;
        d_recs[i] = rec;
    }
}

extern __shared__ char smem[];

__global__ __launch_bounds__(THREADS, 2)
void deform_conv_hmma(const float* __restrict__ bias,
                      float* __restrict__ out)
{
    const uint32_t sbase = smem_u32(smem);
    const int tid  = threadIdx.x;
    const int lane = tid & 31;
    const int w    = tid >> 5;            // 16 warps
    const int y    = blockIdx.y;
    const int xbase = blockIdx.x * POS_PER_BLK;

    // ---- B fill: straight uint4 copy ----
    #pragma unroll
    for (int i = tid; i < (int)(B_BYTES / 16); i += THREADS)
        ((uint4*)(smem + SMEM_B_OFF))[i] = ((const uint4*)d_Btile)[i];

    // ---- Stage 2: gather + fp16x2 blend -> fp16 A tile (records from gmem) ----
    const char* xh = (const char*)d_xh + (uint32_t)lane * 4u;
    {
        #pragma unroll
        for (int p = 0; p < 4; ++p) {
            const int pos = w * 4 + p;
            const uint32_t rm = (uint32_t)pos & 7u;
            const uint32_t arow = SMEM_A_OFF + (uint32_t)pos * ROWB;
            // pair store: kb = j*128 + lane*4 -> block = lane>>2 (j-invariant)
            uint32_t adrP = arow + (((((uint32_t)lane >> 2)) ^ rm) << 4) +
                            ((uint32_t)lane & 3u) * 4u;
            // tap-8 store: kb = 512 + lane*2 -> block = lane>>3  (512>>4=32, 32&7=0)
            const uint32_t adr8 = arow + 512u + (((((uint32_t)lane >> 3)) ^ rm) << 4) +
                                  (((uint32_t)lane * 2u) & 15u);
            const uint4* recp = d_recs + (size_t)(y * WW + xbase + pos) * KK;

            #pragma unroll
            for (int hb = 0; hb < 2; ++hb) {            // taps 4*hb .. 4*hb+3
                uint4 rv[4];
                #pragma unroll
                for (int t = 0; t < 4; ++t)
                    rv[t] = __ldg(recp + hb * 4 + t);

                __half2 h[4][4];
                #pragma unroll
                for (int t = 0; t < 4; ++t) {
                    const uint32_t dxb = rv[t].y & 0xFFFFu;
                    const uint32_t dyb = rv[t].y >> 16;
                    const uint32_t o0 = rv[t].x;
                    const uint32_t o1 = o0 + dxb;
                    const uint32_t o2 = o0 + dyb;
                    const uint32_t o3 = o1 + dyb;
                    h[t][0] = __ldg((const __half2*)(xh + o0));
                    h[t][1] = __ldg((const __half2*)(xh + o1));
                    h[t][2] = __ldg((const __half2*)(xh + o2));
                    h[t][3] = __ldg((const __half2*)(xh + o3));
                }

                __half2 s[4];
                #pragma unroll
                for (int t = 0; t < 4; ++t) {
                    const __half2 wz = *(const __half2*)&rv[t].z;   // (w00, w01)
                    const __half2 ww = *(const __half2*)&rv[t].w;   // (w10, w11)
                    __half2 v = __hmul2(__low2half2(wz), h[t][0]);
                    v = __hfma2(__high2half2(wz), h[t][1], v);
                    v = __hfma2(__low2half2(ww),  h[t][2], v);
                    v = __hfma2(__high2half2(ww), h[t][3], v);
                    s[t] = v;
                }

                // two pair-stores per image half: (s0,s1) and (s2,s3)
                #pragma unroll
                for (int q = 0; q < 2; ++q) {
                    const __half2 lo = __lows2half2(s[2 * q], s[2 * q + 1]);   // batch 0
                    const __half2 hi = __highs2half2(s[2 * q], s[2 * q + 1]);  // batch 1
                    *(__half2*)(smem + adrP) = lo;
                    *(__half2*)(smem + adrP + ROW1_DELTA) = hi;
                    adrP += 128u;
                }
            }

            // tap 8 (single)
            {
                const uint4 rv = __ldg(recp + 8);
                const uint32_t dxb = rv.y & 0xFFFFu;
                const uint32_t dyb = rv.y >> 16;
                const uint32_t o0 = rv.x;
                const __half2 h0 = __ldg((const __half2*)(xh + o0));
                const __half2 h1 = __ldg((const __half2*)(xh + o0 + dxb));
                const __half2 h2 = __ldg((const __half2*)(xh + o0 + dyb));
                const __half2 h3 = __ldg((const __half2*)(xh + o0 + dxb + dyb));
                const __half2 wz = *(const __half2*)&rv.z;
                const __half2 ww = *(const __half2*)&rv.w;
                __half2 v = __hmul2(__low2half2(wz), h0);
                v = __hfma2(__high2half2(wz), h1, v);
                v = __hfma2(__low2half2(ww),  h2, v);
                v = __hfma2(__high2half2(ww), h3, v);
                *(__half*)(smem + adr8) = __low2half(v);
                *(__half*)(smem + adr8 + ROW1_DELTA) = __high2half(v);
            }
        }
    }

    __syncthreads();

    // ---- Phase 3: HMMA GEMM on ALL 16 warps.
    //      warp = (rg = w&7 -> rows 16rg..16rg+15, nh = w>>3 -> n 16nh..16nh+15) ----
    {
        const int rg = w & 7;
        const int nh = w >> 3;
        const int rowbase = rg * 16;

        const int rl  = rowbase + (lane & 7) + (lane & 8);               // A row
        const int kha = (lane >> 4) & 1;                                 // A k-half
        const int nr  = nh * 16 + (lane & 7) + (((lane >> 4) & 1) << 3); // B row
        const int khb = (lane >> 3) & 1;                                 // B k-half

        uint32_t aoff[4], boff[4];
        #pragma unroll
        for (int i = 0; i < 4; ++i) {
            aoff[i] = ((((uint32_t)(2 * i + kha)) & 7u) ^ ((uint32_t)rl & 7u)) << 4;
            boff[i] = ((((uint32_t)(2 * i + khb)) & 7u) ^ ((uint32_t)nr & 7u)) << 4;
        }
        uint32_t a_base = sbase + SMEM_A_OFF + (uint32_t)rl * ROWB;
        uint32_t b_base = sbase + SMEM_B_OFF + (uint32_t)nr * ROWB;

        float d[8];
        #pragma unroll
        for (int i = 0; i < 8; ++i) d[i] = 0.f;

        // 18 K-steps = 4 groups of 4 + 1 group of 2
        #pragma unroll
        for (int g = 0; g < 5; ++g) {
            const int steps = (g < 4) ? 4 : 2;
            #pragma unroll
            for (int i = 0; i < 4; ++i) {
                if (i >= steps) break;
                uint32_t a0, a1, a2, a3;
                LDMATRIX_X4(a0, a1, a2, a3, a_base + aoff[i]);
                uint32_t b0, b1, b2, b3;
                LDMATRIX_X4(b0, b1, b2, b3, b_base + boff[i]);
                MMA16816(d + 0, a0, a1, a2, a3, b0, b1);   // n 16nh+0..7
                MMA16816(d + 4, a0, a1, a2, a3, b2, b3);   // n 16nh+8..15
            }
            a_base += 128u;
            b_base += 128u;
        }

        // ---- Epilogue ----
        const int g = lane >> 2;
        const int t = lane & 3;
        const int R0 = rowbase + g;
        const int R1 = R0 + 8;
        const int b0r = R0 >> 6, p0r = R0 & 63;
        const int b1r = R1 >> 6, p1r = R1 & 63;
        float* o0 = out + ((size_t)(b0r * HH + y) * WW + xbase + p0r) * FF + nh * 16;
        float* o1 = out + ((size_t)(b1r * HH + y) * WW + xbase + p1r) * FF + nh * 16;

        #pragma unroll
        for (int nt = 0; nt < 2; ++nt) {
            const int f0 = nt * 8 + 2 * t;
            const float2 bv = __ldg((const float2*)(bias + nh * 16 + f0));
            float2 v0 = make_float2(d[nt * 4 + 0] + bv.x, d[nt * 4 + 1] + bv.y);
            float2 v1 = make_float2(d[nt * 4 + 2] + bv.x, d[nt * 4 + 3] + bv.y);
            *(float2*)(o0 + f0) = v0;
            *(float2*)(o1 + f0) = v1;
        }
    }
}

extern "C" void kernel_launch(void* const* d_in, const int* in_sizes, int n_in,
                              void* d_out, int out_size)
{
    (void)in_sizes; (void)n_in; (void)out_size;
    const float* x    = (const float*)d_in[0];
    const float* off  = (const float*)d_in[1];
    const float* kern = (const float*)d_in[2];
    const float* bias = (const float*)d_in[3];
    float* out = (float*)d_out;

    // grid must cover NTAPS (records) — the largest index domain
    const int prep_threads = (NTAPS > NPIXC / 4) ? NTAPS : (NPIXC / 4);
    prep_kernel<<<(prep_threads + 255) / 256, 256>>>(x, kern, off);

    cudaFuncSetAttribute(deform_conv_hmma,
                         cudaFuncAttributeMaxDynamicSharedMemorySize, SMEM_TOTAL);

    dim3 grid(WW / POS_PER_BLK, HH);
    deform_conv_hmma<<<grid, THREADS, SMEM_TOTAL>>>(bias, out);
}